// round 2
// baseline (speedup 1.0000x reference)
#include <cuda_runtime.h>
#include <math_constants.h>
#include <math.h>

// Scratch (no allocs allowed): per-block max partials + global 1/max.
#define MAX_BLOCKS 4096
__device__ float g_partial[MAX_BLOCKS];
__device__ float g_invmax;

// Kernel 1: per-pixel winding * min-distance product, plus per-block max.
// contour in shared memory (N+1 entries, wrapped). One thread = one pixel.
__global__ void prod_kernel(const float2* __restrict__ contour, int N,
                            int Sv, float invS, float* __restrict__ out) {
    extern __shared__ float2 sc[];
    __shared__ float red[256];

    const int tid = threadIdx.x;
    for (int i = tid; i < N; i += blockDim.x) sc[i] = contour[i];
    if (tid == 0) sc[N] = contour[0];
    __syncthreads();

    const int p = blockIdx.x * blockDim.x + tid;
    const int npix = Sv * Sv;
    float val = -CUDART_INF_F;

    if (p < npix) {
        // meshgrid 'ij': pixel index p -> (row i, col j), mesh = (i/S, j/S)
        const float px = (float)(p / Sv) * invS;
        const float py = (float)(p % Sv) * invS;
        const float eps = 1e-5f;
        const float k = 100000.0f;

        float2 c0 = sc[0];
        float dx0 = c0.x - px;
        float dy0 = c0.y - py;
        float n0 = sqrtf(dx0 * dx0 + dy0 * dy0);
        float mn = n0;
        float w = 0.0f;

        #pragma unroll 4
        for (int j = 0; j < N; j++) {
            float2 c = sc[j + 1];
            float dx1 = c.x - px;
            float dy1 = c.y - py;
            float n1 = sqrtf(dx1 * dx1 + dy1 * dy1);   // ||roll_diff_j|| == ||diff_{j+1}||
            mn = fminf(mn, n1);

            // cross = diff * roll_diff[...,::-1]; sign = tanh(k*(cross1 - cross0))
            //       = tanh(k*(dy0*dx1 - dx0*dy1))
            float crossv = dy0 * dx1 - dx0 * dy1;
            float sgn = tanhf(k * crossv);

            float dot = dx0 * dx1 + dy0 * dy1;
            float denom = fmaxf(n0, eps) * fmaxf(n1, eps);
            float cosang = dot / denom;
            cosang = fminf(fmaxf(cosang, -1.0f + eps), 1.0f - eps);
            w += sgn * acosf(cosang);

            dx0 = dx1; dy0 = dy1; n0 = n1;
        }

        val = w * 0.15915494309189535f * mn;  // /(2*pi) * min_diff
        out[p] = val;
    }

    // Block max reduction (inactive threads hold -inf).
    red[tid] = val;
    __syncthreads();
    for (int s = 128; s > 0; s >>= 1) {
        if (tid < s) red[tid] = fmaxf(red[tid], red[tid + s]);
        __syncthreads();
    }
    if (tid == 0) g_partial[blockIdx.x] = red[0];
}

// Kernel 2: reduce block partials -> 1/max (single block).
__global__ void max_kernel(int nb) {
    __shared__ float red[1024];
    float m = -CUDART_INF_F;
    for (int i = threadIdx.x; i < nb; i += blockDim.x)
        m = fmaxf(m, g_partial[i]);
    red[threadIdx.x] = m;
    __syncthreads();
    for (int s = 512; s > 0; s >>= 1) {
        if (threadIdx.x < s)
            red[threadIdx.x] = fmaxf(red[threadIdx.x], red[threadIdx.x + s]);
        __syncthreads();
    }
    if (threadIdx.x == 0) g_invmax = 1.0f / red[0];
}

// Kernel 3: normalize out by max.
__global__ void norm_kernel(float* __restrict__ out, int npix) {
    const float inv = g_invmax;
    int i = blockIdx.x * blockDim.x + threadIdx.x;
    if (i < npix) out[i] *= inv;
}

extern "C" void kernel_launch(void* const* d_in, const int* in_sizes, int n_in,
                              void* d_out, int out_size) {
    const float2* contour = (const float2*)d_in[0];
    const int N = in_sizes[0] / 2;   // (N, 2) float32
    // S from out_size = 1*1*S*S (robust; 'size' input may be a device scalar)
    int Sv = (int)(sqrt((double)out_size) + 0.5);
    float invS = 1.0f / (float)Sv;
    int npix = Sv * Sv;

    float* out = (float*)d_out;
    int threads = 256;
    int blocks = (npix + threads - 1) / threads;   // 576 for S=384
    size_t smem = (size_t)(N + 1) * sizeof(float2);

    prod_kernel<<<blocks, threads, smem>>>(contour, N, Sv, invS, out);
    max_kernel<<<1, 1024>>>(blocks);
    norm_kernel<<<blocks, threads>>>(out, npix);
}

// round 5
// speedup vs baseline: 1.7267x; 1.7267x over previous
#include <cuda_runtime.h>
#include <math_constants.h>
#include <math.h>

// Scratch (no allocs allowed): per-block max partials + global 1/max.
#define MAX_BLOCKS 8192
__device__ float g_partial[MAX_BLOCKS];
__device__ float g_invmax;

__device__ __forceinline__ float hw_tanh(float x) {
    float r;
    asm("tanh.approx.f32 %0, %1;" : "=f"(r) : "f"(x));
    return r;
}

// Kernel 1: per-pixel winding * min-distance product, plus per-block max.
// One thread = one pixel. Contour cached in shared memory (N+1, wrapped).
__global__ __launch_bounds__(128) void prod_kernel(
    const float2* __restrict__ contour, int N,
    int Sv, float invS, float* __restrict__ out) {
    extern __shared__ float2 sc[];
    __shared__ float warp_red[4];

    const int tid = threadIdx.x;
    for (int i = tid; i < N; i += blockDim.x) sc[i] = contour[i];
    if (tid == 0) sc[N] = contour[0];
    __syncthreads();

    const int p = blockIdx.x * blockDim.x + tid;
    const int npix = Sv * Sv;
    float val = -CUDART_INF_F;

    if (p < npix) {
        // meshgrid 'ij': pixel p -> (row i, col j), mesh = (i/S, j/S)
        const float px = (float)(p / Sv) * invS;
        const float py = (float)(p % Sv) * invS;
        const float k = 100000.0f;
        // acos(1-1e-5) and acos(-1+1e-5): angle-domain images of the cos clamp
        const float ANG_LO = 4.472136e-3f;
        const float ANG_HI = 3.1371205e0f;   // pi - 4.472136e-3

        float2 c0 = sc[0];
        float dx0 = c0.x - px;
        float dy0 = c0.y - py;
        float mn2 = fmaf(dx0, dx0, dy0 * dy0);
        float w = 0.0f;

        #pragma unroll 4
        for (int j = 0; j < N; j++) {
            float2 c = sc[j + 1];
            float dx1 = c.x - px;
            float dy1 = c.y - py;
            float d2 = fmaf(dx1, dx1, dy1 * dy1);
            mn2 = fminf(mn2, d2);

            // cross = dy0*dx1 - dx0*dy1 ; dot = dx0*dx1 + dy0*dy1
            float crossv = fmaf(dy0, dx1, -dx0 * dy1);
            float dotv   = fmaf(dx0, dx1,  dy0 * dy1);

            float sgn = hw_tanh(k * crossv);

            // angle = acos(dot/(n0*n1)) == atan2(|cross|, dot)
            float ay = fabsf(crossv);
            float ax = fabsf(dotv);
            float num = fminf(ax, ay);
            float den = fmaxf(fmaxf(ax, ay), 1e-37f);
            float a = __fdividef(num, den);          // in [0,1]

            // cephes-style reduction at tan(pi/8)
            bool big = a > 0.41421356f;
            float ar = __fdividef(a - 1.0f, a + 1.0f);
            float xx = big ? ar : a;
            float z = xx * xx;
            float pl = fmaf(fmaf(fmaf(8.05374449538e-2f, z,
                                      -1.38776856032e-1f), z,
                                 1.99777106478e-1f), z,
                            -3.33329491539e-1f);
            float r = fmaf(xx * z, pl, xx);
            if (big) r += 0.78539816340f;            // + pi/4
            if (ay > ax) r = 1.57079632679f - r;     // swap octant
            if (dotv < 0.0f) r = 3.14159265359f - r; // left half-plane
            r = fminf(fmaxf(r, ANG_LO), ANG_HI);     // == cos-domain clip

            w = fmaf(sgn, r, w);

            dx0 = dx1; dy0 = dy1;
        }

        val = w * 0.15915494309189535f * sqrtf(mn2); // /(2*pi) * min_diff
        out[p] = val;
    }

    // Block max reduction: warp shuffle + 4-wide smem
    float m = val;
    #pragma unroll
    for (int o = 16; o > 0; o >>= 1)
        m = fmaxf(m, __shfl_xor_sync(0xffffffffu, m, o));
    if ((tid & 31) == 0) warp_red[tid >> 5] = m;
    __syncthreads();
    if (tid == 0) {
        float bm = fmaxf(fmaxf(warp_red[0], warp_red[1]),
                         fmaxf(warp_red[2], warp_red[3]));
        g_partial[blockIdx.x] = bm;
    }
}

// Kernel 2: reduce block partials -> 1/max (single block).
__global__ void max_kernel(int nb) {
    __shared__ float red[1024];
    float m = -CUDART_INF_F;
    for (int i = threadIdx.x; i < nb; i += blockDim.x)
        m = fmaxf(m, g_partial[i]);
    red[threadIdx.x] = m;
    __syncthreads();
    for (int s = 512; s > 0; s >>= 1) {
        if (threadIdx.x < s)
            red[threadIdx.x] = fmaxf(red[threadIdx.x], red[threadIdx.x + s]);
        __syncthreads();
    }
    if (threadIdx.x == 0) g_invmax = 1.0f / red[0];
}

// Kernel 3: normalize out by max (vectorized float4).
__global__ void norm_kernel(float4* __restrict__ out, int nvec) {
    const float inv = g_invmax;
    int i = blockIdx.x * blockDim.x + threadIdx.x;
    if (i < nvec) {
        float4 v = out[i];
        v.x *= inv; v.y *= inv; v.z *= inv; v.w *= inv;
        out[i] = v;
    }
}

__global__ void norm_tail_kernel(float* __restrict__ out, int start, int npix) {
    const float inv = g_invmax;
    int i = start + blockIdx.x * blockDim.x + threadIdx.x;
    if (i < npix) out[i] *= inv;
}

extern "C" void kernel_launch(void* const* d_in, const int* in_sizes, int n_in,
                              void* d_out, int out_size) {
    const float2* contour = (const float2*)d_in[0];
    const int N = in_sizes[0] / 2;   // (N, 2) float32
    int Sv = (int)(sqrt((double)out_size) + 0.5);
    float invS = 1.0f / (float)Sv;
    int npix = Sv * Sv;

    float* out = (float*)d_out;
    int threads = 128;
    int blocks = (npix + threads - 1) / threads;   // 1152 for S=384
    size_t smem = (size_t)(N + 1) * sizeof(float2);

    prod_kernel<<<blocks, threads, smem>>>(contour, N, Sv, invS, out);
    max_kernel<<<1, 1024>>>(blocks);

    int nvec = npix / 4;
    int vb = (nvec + 255) / 256;
    if (nvec > 0) norm_kernel<<<vb, 256>>>((float4*)out, nvec);
    int tail = npix - nvec * 4;
    if (tail > 0) norm_tail_kernel<<<1, 32>>>(out, nvec * 4, npix);
}

// round 6
// speedup vs baseline: 2.3147x; 1.3405x over previous
#include <cuda_runtime.h>
#include <math_constants.h>
#include <math.h>

// Scratch (no allocs allowed): per-block max partials.
#define MAX_BLOCKS 8192
__device__ float g_partial[MAX_BLOCKS];

__device__ __forceinline__ float hw_tanh(float x) {
    float r;
    asm("tanh.approx.f32 %0, %1;" : "=f"(r) : "f"(x));
    return r;
}

// Kernel 1: per-pixel winding * min-distance product, plus per-block max.
// Fast path: integer winding via ray-crossing (no transcendentals).
// Slow path (rare, |cross| small): exact reference-style tanh/acos correction.
__global__ __launch_bounds__(128) void prod_kernel(
    const float2* __restrict__ contour, int N,
    int Sv, float invS, float* __restrict__ out) {
    extern __shared__ float2 sc[];
    __shared__ float warp_red[4];

    const int tid = threadIdx.x;
    for (int i = tid; i < N; i += blockDim.x) sc[i] = contour[i];
    if (tid == 0) sc[N] = contour[0];
    __syncthreads();

    const int p = blockIdx.x * blockDim.x + tid;
    const int npix = Sv * Sv;
    float val = -CUDART_INF_F;

    if (p < npix) {
        // meshgrid 'ij': pixel p -> (row i, col j), mesh = (i/S, j/S)
        const float px = (float)(p / Sv) * invS;
        const float py = (float)(p % Sv) * invS;
        const float k = 100000.0f;
        // angle-domain images of the cos clamp at 1e-5
        const float ANG_LO = 4.472136e-3f;
        const float ANG_HI = 3.1371205f;          // pi - 4.472136e-3
        // trigger: |cross| < max(CMIN, HC*(d2a+d2b))
        //   HC*(d2a+d2b) >= 4.4721e-3 * n0*n1  (AM-GM)  -> covers cos-clamp region
        //   CMIN -> covers unsaturated tanh (k*|cross| < 10)
        const float HC   = 2.30e-3f;
        const float CMIN = 1.0e-4f;

        float2 c0 = sc[0];
        float dx0 = c0.x - px;
        float dy0 = c0.y - py;
        float d2p = fmaf(dx0, dx0, dy0 * dy0);
        float mn2 = d2p;
        int   W   = 0;       // accumulates -wn_ccw  (sum sign(cross)*theta = 2*pi*W)
        float wc  = 0.0f;    // corrections

        #pragma unroll 4
        for (int j = 0; j < N; j++) {
            float2 c = sc[j + 1];
            float dx1 = c.x - px;
            float dy1 = c.y - py;
            float d2 = fmaf(dx1, dx1, dy1 * dy1);
            mn2 = fminf(mn2, d2);

            // crossv = dy0*dx1 - dx0*dy1  (reference's tanh argument / k)
            float crossv = fmaf(dy0, dx1, -dx0 * dy1);

            // Ray-crossing winding test (isLeft = -crossv):
            // up-straddle (dy0<=0<dy1) & crossv<0 : wn_ccw++ -> W--
            // down-straddle (dy1<=0<dy0) & crossv>0 : wn_ccw-- -> W++
            bool gt0 = dy0 > 0.0f;
            bool gt1 = dy1 > 0.0f;
            if (!gt0 && gt1 && crossv < 0.0f) W--;
            if (gt0 && !gt1 && crossv > 0.0f) W++;

            float s = d2p + d2;
            float tau = fmaxf(CMIN, s * HC);
            if (fabsf(crossv) < tau) {
                // correction = tanh(k*cross)*theta_clamped - sign(cross)*theta_true
                float dotv = fmaf(dx0, dx1, dy0 * dy1);

                // theta_true = atan2(|cross|, dot) (cephes, validated)
                float ay = fabsf(crossv);
                float ax = fabsf(dotv);
                float num = fminf(ax, ay);
                float den = fmaxf(fmaxf(ax, ay), 1e-37f);
                float a = __fdividef(num, den);
                bool big = a > 0.41421356f;
                float ar = __fdividef(a - 1.0f, a + 1.0f);
                float xx = big ? ar : a;
                float z = xx * xx;
                float pl = fmaf(fmaf(fmaf(8.05374449538e-2f, z,
                                          -1.38776856032e-1f), z,
                                     1.99777106478e-1f), z,
                                -3.33329491539e-1f);
                float r = fmaf(xx * z, pl, xx);
                if (big) r += 0.78539816340f;
                if (ay > ax) r = 1.57079632679f - r;
                if (dotv < 0.0f) r = 3.14159265359f - r;

                float rc = fminf(fmaxf(r, ANG_LO), ANG_HI);   // cos-domain clip image
                float sgn = hw_tanh(k * crossv);
                float signed_t = (crossv < 0.0f) ? -r : r;
                wc += fmaf(sgn, rc, -signed_t);
            }

            dx0 = dx1; dy0 = dy1; d2p = d2;
        }

        float wsum = fmaf(6.283185307179586f, (float)W, wc);
        val = wsum * 0.15915494309189535f * sqrtf(mn2);  // /(2*pi) * min_diff
        out[p] = val;
    }

    // Block max reduction: warp shuffle + 4-wide smem
    float m = val;
    #pragma unroll
    for (int o = 16; o > 0; o >>= 1)
        m = fmaxf(m, __shfl_xor_sync(0xffffffffu, m, o));
    if ((tid & 31) == 0) warp_red[tid >> 5] = m;
    __syncthreads();
    if (tid == 0) {
        float bm = fmaxf(fmaxf(warp_red[0], warp_red[1]),
                         fmaxf(warp_red[2], warp_red[3]));
        g_partial[blockIdx.x] = bm;
    }
}

// Kernel 2 (fused max + normalize): every block redundantly reduces the
// per-block partials (L2-resident), then scales its float4 chunk.
__global__ void norm_kernel(float4* __restrict__ out4, float* __restrict__ outf,
                            int nvec, int npix, int nb) {
    __shared__ float red[8];
    __shared__ float s_inv;
    float m = -CUDART_INF_F;
    for (int i = threadIdx.x; i < nb; i += blockDim.x)
        m = fmaxf(m, g_partial[i]);
    #pragma unroll
    for (int o = 16; o > 0; o >>= 1)
        m = fmaxf(m, __shfl_xor_sync(0xffffffffu, m, o));
    if ((threadIdx.x & 31) == 0) red[threadIdx.x >> 5] = m;
    __syncthreads();
    if (threadIdx.x == 0) {
        float bm = red[0];
        #pragma unroll
        for (int i = 1; i < 8; i++) bm = fmaxf(bm, red[i]);
        s_inv = 1.0f / bm;
    }
    __syncthreads();
    const float inv = s_inv;

    int i = blockIdx.x * blockDim.x + threadIdx.x;
    if (i < nvec) {
        float4 v = out4[i];
        v.x *= inv; v.y *= inv; v.z *= inv; v.w *= inv;
        out4[i] = v;
    }
    // tail (npix not divisible by 4)
    int tail = npix - nvec * 4;
    if (blockIdx.x == 0 && threadIdx.x < tail)
        outf[nvec * 4 + threadIdx.x] *= inv;
}

extern "C" void kernel_launch(void* const* d_in, const int* in_sizes, int n_in,
                              void* d_out, int out_size) {
    const float2* contour = (const float2*)d_in[0];
    const int N = in_sizes[0] / 2;   // (N, 2) float32
    int Sv = (int)(sqrt((double)out_size) + 0.5);
    float invS = 1.0f / (float)Sv;
    int npix = Sv * Sv;

    float* out = (float*)d_out;
    int threads = 128;
    int blocks = (npix + threads - 1) / threads;   // 1152 for S=384
    size_t smem = (size_t)(N + 1) * sizeof(float2);

    prod_kernel<<<blocks, threads, smem>>>(contour, N, Sv, invS, out);

    int nvec = npix / 4;
    int nthr = 256;
    int vb = (nvec + nthr - 1) / nthr;
    if (vb < 1) vb = 1;
    norm_kernel<<<vb, nthr>>>((float4*)out, out, nvec, npix, blocks);
}